// round 17
// baseline (speedup 1.0000x reference)
#include <cuda_runtime.h>
#include <mma.h>
#include <cstdint>

using namespace nvcuda;

#define BATCH   4
#define NSEQ    2048
#define DMODEL  1024
#define KDIM    32
#define ROWS    (BATCH * NSEQ)
#define CLAMP_V 10.0f

// Scratch: G row-major [row][32], values pre-rounded to tf32; plus row norms.
__device__ float g_G[(size_t)ROWS * KDIM];
__device__ float g_Gsq[ROWS];

// ---- packed f32x2 helpers ---------------------------------------------------
__device__ __forceinline__ unsigned long long pk2(float a, float b) {
    unsigned long long r;
    asm("mov.b64 %0, {%1, %2};" : "=l"(r) : "f"(a), "f"(b));
    return r;
}
__device__ __forceinline__ void unpk2(unsigned long long v, float& a, float& b) {
    asm("mov.b64 {%0, %1}, %2;" : "=f"(a), "=f"(b) : "l"(v));
}
__device__ __forceinline__ unsigned long long fma2(
    unsigned long long a, unsigned long long b, unsigned long long c) {
    unsigned long long d;
    asm("fma.rn.f32x2 %0, %1, %2, %3;" : "=l"(d) : "l"(a), "l"(b), "l"(c));
    return d;
}
__device__ __forceinline__ unsigned long long add2(
    unsigned long long a, unsigned long long b) {
    unsigned long long d;
    asm("add.rn.f32x2 %0, %1, %2;" : "=l"(d) : "l"(a), "l"(b));
    return d;
}
__device__ __forceinline__ unsigned long long mul2(
    unsigned long long a, unsigned long long b) {
    unsigned long long d;
    asm("mul.rn.f32x2 %0, %1, %2;" : "=l"(d) : "l"(a), "l"(b));
    return d;
}

union F4U { float4 f; unsigned long long u[2]; float s[4]; };

// ---- cp.async helpers -------------------------------------------------------
__device__ __forceinline__ void cpasync16(void* smem_ptr, const void* gmem_ptr) {
    unsigned int s = (unsigned int)__cvta_generic_to_shared(smem_ptr);
    asm volatile("cp.async.cg.shared.global [%0], [%1], 16;\n"
                 :: "r"(s), "l"(gmem_ptr) : "memory");
}
__device__ __forceinline__ void cpasync_commit() {
    asm volatile("cp.async.commit_group;\n" ::: "memory");
}
__device__ __forceinline__ void cpasync_wait1() {
    asm volatile("cp.async.wait_group 1;\n" ::: "memory");
}
__device__ __forceinline__ void cpasync_wait0() {
    asm volatile("cp.async.wait_group 0;\n" ::: "memory");
}

template <class Frag>
__device__ __forceinline__ void frag_to_tf32(Frag& f) {
    #pragma unroll
    for (int i = 0; i < f.num_elements; i++)
        f.x[i] = wmma::__float_to_tf32(f.x[i]);
}

// ---------------------------------------------------------------------------
// Kernel 1: G = H @ W^T via tf32 WMMA. 256 blocks x 32 rows, 128 threads
// (4 warps = 2 m-tiles x 2 n-tiles, 1 WMMA tile each). 3-stage cp.async
// over d-chunks of 32. Epilogue: round G to tf32, compute row norms.
// ---------------------------------------------------------------------------
#define K1_STAGE_D 32

__device__ __forceinline__ void k1_issue_stage(
    int s, int dc, int tid, int r0,
    const float* __restrict__ H, const float* __restrict__ W,
    float (*Hs)[32][40], float (*Ws)[32][40])
{
    #pragma unroll
    for (int p = 0; p < 2; p++) {
        const int e  = tid + p * 128;
        const int rr = e >> 3;
        const int cc = (e & 7) * 4;
        cpasync16(&Hs[s][rr][cc], H + (size_t)(r0 + rr) * DMODEL + dc + cc);
        cpasync16(&Ws[s][rr][cc], W + (size_t)rr * DMODEL + dc + cc);
    }
    cpasync_commit();
}

__global__ void __launch_bounds__(128) k1_proj(
    const float* __restrict__ H, const float* __restrict__ W)
{
    __shared__ float Hs[3][32][40];
    __shared__ float Ws[3][32][40];
    __shared__ float Gsm[32][36];

    const int tid = threadIdx.x;
    const int r0  = blockIdx.x * 32;
    const int w   = tid >> 5;
    const int mt  = w & 1;
    const int nt  = w >> 1;

    k1_issue_stage(0, 0, tid, r0, H, W, Hs, Ws);
    k1_issue_stage(1, K1_STAGE_D, tid, r0, H, W, Hs, Ws);

    wmma::fragment<wmma::accumulator, 16, 16, 8, float> acc;
    wmma::fill_fragment(acc, 0.0f);

    const int NCHUNK = DMODEL / K1_STAGE_D;   // 32
    for (int c = 0; c < NCHUNK; c++) {
        if (c < NCHUNK - 1) cpasync_wait1(); else cpasync_wait0();
        __syncthreads();

        if (c + 2 < NCHUNK)
            k1_issue_stage((c + 2) % 3, (c + 2) * K1_STAGE_D, tid, r0, H, W, Hs, Ws);

        const int buf = c % 3;
        #pragma unroll
        for (int ks = 0; ks < K1_STAGE_D / 8; ks++) {
            wmma::fragment<wmma::matrix_a, 16, 16, 8, wmma::precision::tf32,
                           wmma::row_major> a;
            wmma::fragment<wmma::matrix_b, 16, 16, 8, wmma::precision::tf32,
                           wmma::col_major> bf;
            wmma::load_matrix_sync(a, &Hs[buf][mt * 16][ks * 8], 40);
            wmma::load_matrix_sync(bf, &Ws[buf][nt * 16][ks * 8], 40);
            frag_to_tf32(a);
            frag_to_tf32(bf);
            wmma::mma_sync(acc, a, bf, acc);
        }
    }

    // Stage to smem, round to tf32, compute norms, write out.
    wmma::store_matrix_sync(&Gsm[mt * 16][nt * 16], acc, 36, wmma::mem_row_major);
    __syncthreads();

    #pragma unroll
    for (int e = tid; e < 32 * 32; e += 128) {
        const int r = e >> 5;
        const int k = e & 31;
        Gsm[r][k] = wmma::__float_to_tf32(Gsm[r][k]);
    }
    __syncthreads();

    if (tid < 32) {
        float s = 0.f;
        #pragma unroll
        for (int k = 0; k < KDIM; k++) { const float v = Gsm[tid][k]; s += v * v; }
        g_Gsq[r0 + tid] = s;
    }
    #pragma unroll
    for (int e = tid; e < 32 * 8; e += 128) {      // 256 float4
        const int r  = e >> 3;
        const int c4 = (e & 7) * 4;
        *(float4*)(g_G + (size_t)(r0 + r) * KDIM + c4) = *(const float4*)&Gsm[r][c4];
    }
}

// ---------------------------------------------------------------------------
// Kernel 2: 128x128 tile, grid 1024, 256 threads (8 warps). G is already
// tf32-rounded -> NO conversions in the gram loop. Two-pass Cs staging
// (64 j-cols per pass) keeps smem at 72.7 KB -> 3 blocks/SM.
// ---------------------------------------------------------------------------
#define K2_SMEM_BYTES (2 * 128 * 36 * 4 + 128 * 68 * 4 + 2 * 128 * 4)

__global__ void __launch_bounds__(256) k2_bias(
    const float* __restrict__ Bprev,
    const float* __restrict__ alpha_p,
    const float* __restrict__ beta_p,
    float* __restrict__ out)
{
    extern __shared__ float sm[];
    float (*Gi)[36] = (float(*)[36])sm;                    // 128 x 36
    float (*Gj)[36] = (float(*)[36])(sm + 128 * 36);       // 128 x 36
    float (*Cs)[68] = (float(*)[68])(sm + 2 * 128 * 36);   // 128 x 68
    float* sqi = sm + 2 * 128 * 36 + 128 * 68;             // 128
    float* sqj = sqi + 128;                                // 128

    const int b   = blockIdx.z;
    const int i0  = blockIdx.y * 128;
    const int j0  = blockIdx.x * 128;
    const int gi0 = b * NSEQ + i0;
    const int gj0 = b * NSEQ + j0;
    const int tid = threadIdx.x;

    const float alpha = *alpha_p;
    const float beta  = *beta_p;

    // Tile loads (coalesced f4) + norms from precomputed g_Gsq.
    #pragma unroll
    for (int e = tid; e < 128 * 8; e += 256) {
        const int r  = e >> 3;
        const int c4 = (e & 7) * 4;
        *(float4*)&Gi[r][c4] = *(const float4*)(g_G + (size_t)(gi0 + r) * KDIM + c4);
        *(float4*)&Gj[r][c4] = *(const float4*)(g_G + (size_t)(gj0 + r) * KDIM + c4);
    }
    if (tid < 128)      sqi[tid]       = g_Gsq[gi0 + tid];
    else                sqj[tid - 128] = g_Gsq[gj0 + tid - 128];
    __syncthreads();

    const int w  = tid >> 5;           // warp = m-tile (0..7)
    const int ti = tid >> 4;           // 0..15: epilogue row base
    const int tj = tid & 15;           // 0..15: epilogue f4-col
    const int jb = tj * 4;

    const unsigned long long alpha2   = pk2(alpha, alpha);
    const unsigned long long negbeta2 = pk2(-beta, -beta);
    const unsigned long long negtwo2  = pk2(-2.0f, -2.0f);

    #pragma unroll
    for (int pass = 0; pass < 2; pass++) {
        // Gram: warp w -> m-tile w, n-tiles pass*4 .. pass*4+3.
        wmma::fragment<wmma::accumulator, 16, 16, 8, float> acc[4];
        #pragma unroll
        for (int nt = 0; nt < 4; nt++) wmma::fill_fragment(acc[nt], 0.0f);

        #pragma unroll
        for (int ks = 0; ks < KDIM / 8; ks++) {
            wmma::fragment<wmma::matrix_a, 16, 16, 8, wmma::precision::tf32,
                           wmma::row_major> a;
            wmma::load_matrix_sync(a, &Gi[w * 16][ks * 8], 36);
            #pragma unroll
            for (int nt = 0; nt < 4; nt++) {
                wmma::fragment<wmma::matrix_b, 16, 16, 8, wmma::precision::tf32,
                               wmma::col_major> bf;
                wmma::load_matrix_sync(bf, &Gj[(pass * 4 + nt) * 16][ks * 8], 36);
                wmma::mma_sync(acc[nt], a, bf, acc[nt]);
            }
        }
        #pragma unroll
        for (int nt = 0; nt < 4; nt++)
            wmma::store_matrix_sync(&Cs[w * 16][nt * 16], acc[nt], 68,
                                    wmma::mem_row_major);
        __syncthreads();

        // Epilogue for j-cols [pass*64, pass*64+64): packed over col pairs.
        const int jg = pass * 64 + jb;
        unsigned long long sj2a = pk2(sqj[jg],     sqj[jg + 1]);
        unsigned long long sj2b = pk2(sqj[jg + 2], sqj[jg + 3]);

        #pragma unroll
        for (int r = 0; r < 8; r++) {
            const int row = ti + 16 * r;
            const unsigned long long si2 = pk2(sqi[row], sqi[row]);
            const size_t goff = ((size_t)b * NSEQ + (i0 + row)) * NSEQ + j0 + jg;

            F4U cv, bv;
            cv.f = *(const float4*)&Cs[row][jb];
            bv.f = __ldcs((const float4*)(Bprev + goff));

            const unsigned long long rawa =
                fma2(negtwo2, cv.u[0], add2(si2, sj2a));
            const unsigned long long rawb =
                fma2(negtwo2, cv.u[1], add2(si2, sj2b));
            const unsigned long long aba = mul2(alpha2, bv.u[0]);
            const unsigned long long abb = mul2(alpha2, bv.u[1]);
            const unsigned long long ta  = fma2(negbeta2, rawa, aba);
            const unsigned long long tb  = fma2(negbeta2, rawb, abb);

            float a0, a1, a2, a3, t0, t1, t2, t3;
            unpk2(aba, a0, a1); unpk2(abb, a2, a3);
            unpk2(ta, t0, t1);  unpk2(tb, t2, t3);

            F4U rv;
            rv.s[0] = fminf(fmaxf(fminf(a0, t0), -CLAMP_V), CLAMP_V);
            rv.s[1] = fminf(fmaxf(fminf(a1, t1), -CLAMP_V), CLAMP_V);
            rv.s[2] = fminf(fmaxf(fminf(a2, t2), -CLAMP_V), CLAMP_V);
            rv.s[3] = fminf(fmaxf(fminf(a3, t3), -CLAMP_V), CLAMP_V);
            __stcs((float4*)(out + goff), rv.f);
        }
        __syncthreads();   // Cs reused next pass
    }
}

// ---------------------------------------------------------------------------
extern "C" void kernel_launch(void* const* d_in, const int* in_sizes, int n_in,
                              void* d_out, int out_size)
{
    const float* H     = (const float*)d_in[0];
    const float* Bprev = (const float*)d_in[1];
    const float* W     = (const float*)d_in[2];
    const float* alpha = (const float*)d_in[3];
    const float* beta  = (const float*)d_in[4];
    float* out = (float*)d_out;

    static bool attr_set = false;
    if (!attr_set) {
        cudaFuncSetAttribute(k2_bias, cudaFuncAttributeMaxDynamicSharedMemorySize,
                             K2_SMEM_BYTES);
        attr_set = true;
    }

    k1_proj<<<ROWS / 32, 128>>>(H, W);

    dim3 g2(NSEQ / 128, NSEQ / 128, BATCH);
    k2_bias<<<g2, 256, K2_SMEM_BYTES>>>(Bprev, alpha, beta, out);
}